// round 11
// baseline (speedup 1.0000x reference)
#include <cuda_runtime.h>
#include <cstdint>

// Cross attention B=8, Tq=Tk=2048, D=1024, fp32.
// All 6 GEMMs via mma.sync m16n8k8 tf32. K-dim stored with p16 permutation
// ([k0,k4,k8,k12,k1,k5,...] per 16-block) so ONE LDS.128 feeds TWO ks steps.
// 128x128 tiles, 2 CTAs/SM, ROWW=48 (conflict-free LDS.128 phases).

#define BATCH 8
#define TSEQ  2048
#define EMB   1024
#define MTOT  (BATCH * TSEQ)          // 16384
#define NELEM ((size_t)MTOT * EMB)    // 16M

// ---------------- scratch (__device__ globals; no allocation) --------------
__device__ float g_T[NELEM];
__device__ float g_Src[NELEM];
__device__ float g_W[4u * EMB * EMB];
__device__ float g_Q[NELEM];
__device__ float g_K[NELEM];
__device__ float g_Vt[NELEM];                        // [B][EMB][TSEQ]
__device__ float g_S[(size_t)BATCH * TSEQ * TSEQ];   // scores -> P in place
__device__ float g_O[NELEM];

// ---------------- helpers --------------------------------------------------
__device__ __forceinline__ uint32_t smem_u32(const void* p) {
    uint32_t a;
    asm("{ .reg .u64 t; cvta.to.shared.u64 t, %1; cvt.u32.u64 %0, t; }" : "=r"(a) : "l"(p));
    return a;
}
__device__ __forceinline__ float tf32r(float x) {
    uint32_t u;
    asm("cvt.rna.tf32.f32 %0, %1;" : "=r"(u) : "f"(x));
    return __uint_as_float(u);
}
// in-block position of true index c under p16 (self-inverse)
__device__ __forceinline__ int p16i(int c) {   // c in [0,16)
    return ((c & 3) << 2) | (c >> 2);
}
#define CP_ASYNC16(dst, src) \
    asm volatile("cp.async.cg.shared.global [%0], [%1], 16;" :: "r"(dst), "l"(src) : "memory")
#define CP_COMMIT() asm volatile("cp.async.commit_group;" ::: "memory")
#define CP_WAIT0()  asm volatile("cp.async.wait_group 0;" ::: "memory")

#define MMA_TF32(c, a0, a1, a2, a3, b0, b1) \
    asm volatile("mma.sync.aligned.m16n8k8.row.col.f32.tf32.tf32.f32 " \
        "{%0,%1,%2,%3}, {%4,%5,%6,%7}, {%8,%9}, {%0,%1,%2,%3};" \
        : "+f"((c)[0]), "+f"((c)[1]), "+f"((c)[2]), "+f"((c)[3]) \
        : "r"(a0), "r"(a1), "r"(a2), "r"(a3), "r"(b0), "r"(b1))

// ---------------------------------------------------------------------------
// tf32 GEMM (all-NT): C[M,N] = alpha * A[M,K] @ B[N,K]^T (+ bias[N])
// A,B stored with k-dim p16-permuted. BM=128 BN=128 BK=32, 256 threads =
// 8 warps (2 M x 4 N), warp tile 64x32. 2-stage cp.async, one barrier/iter,
// 2 CTAs/SM. Rows padded to 48 floats (LDS.128 conflict-free).
// MODE 0: fp32 out (true cols). MODE 1: tf32-rounded out, cols p16-permuted.
// MODE 2: rounded + transposed (Vt[b][col][p16(tok)]).
// ---------------------------------------------------------------------------
#define BM 128
#define BN 128
#define BK 32
#define ROWW 48
#define STG_FLOATS ((BM + BN) * ROWW)   // 12288
#define STG_BYTES  (STG_FLOATS * 4)     // 49152
#define GEMM_SMEM  (2 * STG_BYTES)      // 98304

template <int MODE, bool HAS_BIAS>
__global__ __launch_bounds__(256, 2)
void tf32_gemm(const float* __restrict__ A, const float* __restrict__ B,
               const float* __restrict__ bias, float* __restrict__ C,
               int M, int N, int K, float alpha,
               size_t sA, size_t sB, size_t sC)
{
    extern __shared__ float sm[];
    const uint32_t sb = smem_u32(sm);

    const int tid  = threadIdx.x;
    const int wid  = tid >> 5, lane = tid & 31;
    const int g    = lane >> 2, t4 = lane & 3;
    const int wm   = wid & 1,  wn = wid >> 1;

    const int m0 = blockIdx.y * BM;
    const int n0 = blockIdx.x * BN;
    A += (size_t)blockIdx.z * sA + (size_t)m0 * K;
    B += (size_t)blockIdx.z * sB + (size_t)n0 * K;

    auto load_stage = [&](int kt, int s) {
        const uint32_t st = sb + s * STG_BYTES;
        const int k0 = kt * BK;
#pragma unroll
        for (int i = 0; i < 4; i++) {          // A: 128 rows x 8 chunks
            int id = tid + i * 256, r = id >> 3, c = id & 7;
            CP_ASYNC16(st + (r * ROWW + c * 4) * 4, A + (size_t)r * K + k0 + c * 4);
        }
#pragma unroll
        for (int i = 0; i < 4; i++) {          // B: 128 rows x 8 chunks
            int id = tid + i * 256, r = id >> 3, c = id & 7;
            CP_ASYNC16(st + (BM * ROWW + r * ROWW + c * 4) * 4,
                       B + (size_t)r * K + k0 + c * 4);
        }
        CP_COMMIT();
    };

    // fragment base pointers: word 4*t4 of each 16-k block holds true
    // k = {t4, t4+4, t4+8, t4+12}  (x,y -> ks even; z,w -> ks odd)
    const float* aBase = sm + (wm * 64 + g) * ROWW + 4 * t4;
    const float* bBase = sm + BM * ROWW + (wn * 32 + g) * ROWW + 4 * t4;

    float acc[4][4][4];
#pragma unroll
    for (int mi = 0; mi < 4; mi++)
#pragma unroll
        for (int ni = 0; ni < 4; ni++)
#pragma unroll
            for (int r = 0; r < 4; r++) acc[mi][ni][r] = 0.0f;

    const int KT = K / BK;
    load_stage(0, 0);

    for (int kt = 0; kt < KT; kt++) {
        CP_WAIT0();
        __syncthreads();
        if (kt + 1 < KT) load_stage(kt + 1, (kt + 1) & 1);

        const float* As = aBase + (kt & 1) * STG_FLOATS;
        const float* Bs = bBase + (kt & 1) * STG_FLOATS;

#pragma unroll
        for (int kb = 0; kb < 2; kb++) {       // two 16-k blocks per stage
            float4 alo[4], ahi[4], bq[4];
#pragma unroll
            for (int mi = 0; mi < 4; mi++) {
                alo[mi] = *reinterpret_cast<const float4*>(As + mi * 16 * ROWW + kb * 16);
                ahi[mi] = *reinterpret_cast<const float4*>(As + mi * 16 * ROWW + 8 * ROWW + kb * 16);
            }
#pragma unroll
            for (int ni = 0; ni < 4; ni++)
                bq[ni] = *reinterpret_cast<const float4*>(Bs + ni * 8 * ROWW + kb * 16);

            // ks even (k = t4, t4+4) -> x,y
#pragma unroll
            for (int mi = 0; mi < 4; mi++)
#pragma unroll
                for (int ni = 0; ni < 4; ni++)
                    MMA_TF32(acc[mi][ni],
                             __float_as_uint(alo[mi].x), __float_as_uint(ahi[mi].x),
                             __float_as_uint(alo[mi].y), __float_as_uint(ahi[mi].y),
                             __float_as_uint(bq[ni].x),  __float_as_uint(bq[ni].y));
            // ks odd (k = t4+8, t4+12) -> z,w
#pragma unroll
            for (int mi = 0; mi < 4; mi++)
#pragma unroll
                for (int ni = 0; ni < 4; ni++)
                    MMA_TF32(acc[mi][ni],
                             __float_as_uint(alo[mi].z), __float_as_uint(ahi[mi].z),
                             __float_as_uint(alo[mi].w), __float_as_uint(ahi[mi].w),
                             __float_as_uint(bq[ni].z),  __float_as_uint(bq[ni].w));
        }
    }

    // ---- epilogue ----
    if (MODE == 2) {
        // transposed + rounded: Vt[b][col][p16(tok)]
        float* Cb = C + (size_t)(m0 / TSEQ) * EMB * TSEQ;
        const int pg = p16i(g);                 // pos of row g in its 16-block
        const int tokbase = (m0 % TSEQ) + wm * 64;
#pragma unroll
        for (int mi = 0; mi < 4; mi++) {
            const int tok0 = tokbase + mi * 16 + pg;       // row g
            const int tok8 = tok0 + 2;                     // row g+8 -> pos+2
#pragma unroll
            for (int ni = 0; ni < 4; ni++) {
                const int col = n0 + wn * 32 + ni * 8 + t4 * 2;
                float b0 = HAS_BIAS ? __ldg(bias + col)     : 0.0f;
                float b1 = HAS_BIAS ? __ldg(bias + col + 1) : 0.0f;
                Cb[(size_t)col * TSEQ + tok0]       = tf32r(acc[mi][ni][0] * alpha + b0);
                Cb[(size_t)(col + 1) * TSEQ + tok0] = tf32r(acc[mi][ni][1] * alpha + b1);
                Cb[(size_t)col * TSEQ + tok8]       = tf32r(acc[mi][ni][2] * alpha + b0);
                Cb[(size_t)(col + 1) * TSEQ + tok8] = tf32r(acc[mi][ni][3] * alpha + b1);
            }
        }
    } else if (MODE == 1) {
        // rounded out, columns stored p16-permuted (they are a k-dim downstream)
        C += (size_t)blockIdx.z * sC;
#pragma unroll
        for (int mi = 0; mi < 4; mi++) {
            const int row = m0 + wm * 64 + mi * 16 + g;
#pragma unroll
            for (int ni = 0; ni < 4; ni++) {
                const int colb16 = n0 + wn * 32 + (ni >> 1) * 16;   // 16-block base
                const int c0 = (ni & 1) * 8 + 2 * t4;               // true in-block
                const int c1 = c0 + 1;
                float b0 = HAS_BIAS ? __ldg(bias + colb16 + c0) : 0.0f;
                float b1 = HAS_BIAS ? __ldg(bias + colb16 + c1) : 0.0f;
                const int q0 = colb16 + p16i(c0);
                const int q1 = colb16 + p16i(c1);
                C[(size_t)row * N + q0]       = tf32r(acc[mi][ni][0] * alpha + b0);
                C[(size_t)row * N + q1]       = tf32r(acc[mi][ni][1] * alpha + b1);
                C[(size_t)(row + 8) * N + q0] = tf32r(acc[mi][ni][2] * alpha + b0);
                C[(size_t)(row + 8) * N + q1] = tf32r(acc[mi][ni][3] * alpha + b1);
            }
        }
    } else {
        // MODE 0: plain fp32, true column order
        C += (size_t)blockIdx.z * sC;
#pragma unroll
        for (int mi = 0; mi < 4; mi++) {
            const int row = m0 + wm * 64 + mi * 16 + g;
#pragma unroll
            for (int ni = 0; ni < 4; ni++) {
                const int col = n0 + wn * 32 + ni * 8 + t4 * 2;
                float b0 = HAS_BIAS ? __ldg(bias + col)     : 0.0f;
                float b1 = HAS_BIAS ? __ldg(bias + col + 1) : 0.0f;
                float f0 = acc[mi][ni][0] * alpha + b0;
                float f1 = acc[mi][ni][1] * alpha + b1;
                float f2 = acc[mi][ni][2] * alpha + b0;
                float f3 = acc[mi][ni][3] * alpha + b1;
                *reinterpret_cast<float2*>(C + (size_t)row * N + col)       = make_float2(f0, f1);
                *reinterpret_cast<float2*>(C + (size_t)(row + 8) * N + col) = make_float2(f2, f3);
            }
        }
    }
}

// ---------------------------------------------------------------------------
// rounding: tf32-round AND p16-permute (16 elements = one block per thread)
// out float4 j holds true elems {j, j+4, j+8, j+12}
// ---------------------------------------------------------------------------
__device__ __forceinline__ void round_perm16(const float4 i[4], float4 o[4])
{
    const float* e = reinterpret_cast<const float*>(i);
#pragma unroll
    for (int j = 0; j < 4; j++)
        o[j] = make_float4(tf32r(e[j]), tf32r(e[j + 4]), tf32r(e[j + 8]), tf32r(e[j + 12]));
}

__global__ void round_act_kernel(const float4* __restrict__ a, float4* __restrict__ ya,
                                 const float4* __restrict__ b, float4* __restrict__ yb,
                                 int n16)
{
    int i = blockIdx.x * blockDim.x + threadIdx.x;
    if (i >= n16) return;
    const float4* x = blockIdx.y ? b : a;
    float4*       y = blockIdx.y ? yb : ya;
    float4 in[4], o[4];
#pragma unroll
    for (int j = 0; j < 4; j++) in[j] = x[4 * i + j];
    round_perm16(in, o);
#pragma unroll
    for (int j = 0; j < 4; j++) y[4 * i + j] = o[j];
}

__global__ void round_w_kernel(const float4* __restrict__ w0, const float4* __restrict__ w1,
                               const float4* __restrict__ w2, const float4* __restrict__ w3,
                               float4* __restrict__ y, int n16)
{
    int i = blockIdx.x * blockDim.x + threadIdx.x;
    if (i >= n16) return;
    const float4* src = (blockIdx.y == 0) ? w0 : (blockIdx.y == 1) ? w1
                      : (blockIdx.y == 2) ? w2 : w3;
    float4 in[4], o[4];
#pragma unroll
    for (int j = 0; j < 4; j++) in[j] = src[4 * i + j];
    round_perm16(in, o);
#pragma unroll
    for (int j = 0; j < 4; j++) y[(size_t)blockIdx.y * 4 * n16 + 4 * i + j] = o[j];
}

// ---------------------------------------------------------------------------
// softmax over 2048-length rows (in place): 128 threads/row, 16 elems/thread.
// Reads true-order S, writes tf32-rounded P with p16-permuted columns.
// ---------------------------------------------------------------------------
__device__ __forceinline__ float blk_red_max4(float v) {
    __shared__ float sh[4]; __shared__ float res;
    const int lane = threadIdx.x & 31, warp = threadIdx.x >> 5;
#pragma unroll
    for (int o = 16; o > 0; o >>= 1) v = fmaxf(v, __shfl_xor_sync(0xffffffffu, v, o));
    if (lane == 0) sh[warp] = v;
    __syncthreads();
    if (warp == 0) {
        float w = (lane < 4) ? sh[lane] : -3.0e38f;
#pragma unroll
        for (int o = 2; o > 0; o >>= 1) w = fmaxf(w, __shfl_xor_sync(0xffffffffu, w, o));
        if (lane == 0) res = w;
    }
    __syncthreads();
    return res;
}
__device__ __forceinline__ float blk_red_sum4(float v) {
    __shared__ float sh[4]; __shared__ float res;
    const int lane = threadIdx.x & 31, warp = threadIdx.x >> 5;
#pragma unroll
    for (int o = 16; o > 0; o >>= 1) v += __shfl_xor_sync(0xffffffffu, v, o);
    if (lane == 0) sh[warp] = v;
    __syncthreads();
    if (warp == 0) {
        float w = (lane < 4) ? sh[lane] : 0.0f;
#pragma unroll
        for (int o = 2; o > 0; o >>= 1) w += __shfl_xor_sync(0xffffffffu, w, o);
        if (lane == 0) res = w;
    }
    __syncthreads();
    return res;
}

__global__ __launch_bounds__(128)
void softmax_kernel(float* __restrict__ S)
{
    float4* row = reinterpret_cast<float4*>(S + (size_t)blockIdx.x * TSEQ);
    const int t = threadIdx.x;

    float4 v[4];
#pragma unroll
    for (int j = 0; j < 4; j++) v[j] = row[4 * t + j];

    float mx = -3.0e38f;
#pragma unroll
    for (int j = 0; j < 4; j++)
        mx = fmaxf(mx, fmaxf(fmaxf(v[j].x, v[j].y), fmaxf(v[j].z, v[j].w)));
    mx = blk_red_max4(mx);

    float s = 0.0f;
#pragma unroll
    for (int j = 0; j < 4; j++) {
        v[j].x = __expf(v[j].x - mx); v[j].y = __expf(v[j].y - mx);
        v[j].z = __expf(v[j].z - mx); v[j].w = __expf(v[j].w - mx);
        s += (v[j].x + v[j].y) + (v[j].z + v[j].w);
    }
    s = blk_red_sum4(s);
    const float inv = 1.0f / s;
#pragma unroll
    for (int j = 0; j < 4; j++) {
        v[j].x *= inv; v[j].y *= inv; v[j].z *= inv; v[j].w *= inv;
    }

    float4 o[4];
    round_perm16(v, o);
#pragma unroll
    for (int j = 0; j < 4; j++) row[4 * t + j] = o[j];
}

// ---------------------------------------------------------------------------
extern "C" void kernel_launch(void* const* d_in, const int* in_sizes, int n_in,
                              void* d_out, int out_size)
{
    const float* target = (const float*)d_in[0];
    const float* source = (const float*)d_in[1];
    const float* Wq = (const float*)d_in[2];
    const float* bq = (const float*)d_in[3];
    const float* Wk = (const float*)d_in[4];
    const float* bk = (const float*)d_in[5];
    const float* Wv = (const float*)d_in[6];
    const float* bv = (const float*)d_in[7];
    const float* Wo = (const float*)d_in[8];
    const float* bo = (const float*)d_in[9];
    float* out = (float*)d_out;

    float *T, *Src, *W, *Q, *Kb, *Vt, *S, *O;
    cudaGetSymbolAddress((void**)&T,   g_T);
    cudaGetSymbolAddress((void**)&Src, g_Src);
    cudaGetSymbolAddress((void**)&W,   g_W);
    cudaGetSymbolAddress((void**)&Q,   g_Q);
    cudaGetSymbolAddress((void**)&Kb,  g_K);
    cudaGetSymbolAddress((void**)&Vt,  g_Vt);
    cudaGetSymbolAddress((void**)&S,   g_S);
    cudaGetSymbolAddress((void**)&O,   g_O);

    cudaFuncSetAttribute(tf32_gemm<0, false>, cudaFuncAttributeMaxDynamicSharedMemorySize, GEMM_SMEM);
    cudaFuncSetAttribute(tf32_gemm<0, true>,  cudaFuncAttributeMaxDynamicSharedMemorySize, GEMM_SMEM);
    cudaFuncSetAttribute(tf32_gemm<1, false>, cudaFuncAttributeMaxDynamicSharedMemorySize, GEMM_SMEM);
    cudaFuncSetAttribute(tf32_gemm<1, true>,  cudaFuncAttributeMaxDynamicSharedMemorySize, GEMM_SMEM);
    cudaFuncSetAttribute(tf32_gemm<2, true>,  cudaFuncAttributeMaxDynamicSharedMemorySize, GEMM_SMEM);

    // launch 0: round+perm activations; launch 1: round+perm 4 weights
    {
        dim3 ga((unsigned)(NELEM / 16 / 256), 2, 1);
        round_act_kernel<<<ga, 256>>>((const float4*)target, (float4*)T,
                                      (const float4*)source, (float4*)Src,
                                      (int)(NELEM / 16));
        dim3 gw((unsigned)(EMB * EMB / 16 / 256), 4, 1);
        round_w_kernel<<<gw, 256>>>((const float4*)Wq, (const float4*)Wk,
                                    (const float4*)Wv, (const float4*)Wo,
                                    (float4*)W, EMB * EMB / 16);
    }

    const float scale = 1.0f / 32.0f;  // 1/sqrt(1024)

    // launches 2-4: projections
    {
        dim3 grd(EMB / BN, MTOT / BM, 1);
        tf32_gemm<1, true><<<grd, 256, GEMM_SMEM>>>(T,   W + 0u * EMB * EMB, bq, Q,
                                                    MTOT, EMB, EMB, 1.0f, 0, 0, 0);
        tf32_gemm<1, true><<<grd, 256, GEMM_SMEM>>>(Src, W + 1u * EMB * EMB, bk, Kb,
                                                    MTOT, EMB, EMB, 1.0f, 0, 0, 0);
        tf32_gemm<2, true><<<grd, 256, GEMM_SMEM>>>(Src, W + 2u * EMB * EMB, bv, Vt,
                                                    MTOT, EMB, EMB, 1.0f, 0, 0, 0);
    }

    // launch 5 (ncu -s 5 -c 1 captures this): S = Q @ K^T / 32
    {
        dim3 grd(TSEQ / BN, TSEQ / BM, BATCH);
        tf32_gemm<0, false><<<grd, 256, GEMM_SMEM>>>(Q, Kb, nullptr, S,
            TSEQ, TSEQ, EMB, scale,
            (size_t)TSEQ * EMB, (size_t)TSEQ * EMB, (size_t)TSEQ * TSEQ);
    }

    // P = softmax(S) in place (rounded + p16-permuted)
    softmax_kernel<<<BATCH * TSEQ, 128>>>(S);

    // O = P @ Vt^T (batched, K=2048)
    {
        dim3 grd(EMB / BN, TSEQ / BM, BATCH);
        tf32_gemm<1, false><<<grd, 256, GEMM_SMEM>>>(S, Vt, nullptr, O,
            TSEQ, EMB, TSEQ, 1.0f,
            (size_t)TSEQ * TSEQ, (size_t)EMB * TSEQ, (size_t)TSEQ * EMB);
    }

    // out = O @ Wo^T + bo (fp32, true order)
    {
        dim3 grd(EMB / BN, MTOT / BM, 1);
        tf32_gemm<0, true><<<grd, 256, GEMM_SMEM>>>(O, W + 3u * EMB * EMB, bo, out,
                                                    MTOT, EMB, EMB, 1.0f, 0, 0, 0);
    }
}

// round 12
// speedup vs baseline: 1.1188x; 1.1188x over previous
#include <cuda_runtime.h>
#include <cstdint>

// Cross attention B=8, Tq=Tk=2048, D=1024, fp32.
// All 6 GEMMs via mma.sync m16n8k8 tf32. K-dim stored PERMUTED (p8) so
// fragment loads are LDS.64. 128x128 tiles, 2 CTAs/SM, XOR-swizzled smem
// (no padding) -> 32KB stages -> 3-stage cp.async pipeline, prefetch dist 2.

#define BATCH 8
#define TSEQ  2048
#define EMB   1024
#define MTOT  (BATCH * TSEQ)          // 16384
#define NELEM ((size_t)MTOT * EMB)    // 16M

// ---------------- scratch (__device__ globals; no allocation) --------------
__device__ float g_T[NELEM];
__device__ float g_Src[NELEM];
__device__ float g_W[4u * EMB * EMB];
__device__ float g_Q[NELEM];
__device__ float g_K[NELEM];
__device__ float g_Vt[NELEM];                        // [B][EMB][TSEQ]
__device__ float g_S[(size_t)BATCH * TSEQ * TSEQ];   // scores -> P in place
__device__ float g_O[NELEM];

// ---------------- helpers --------------------------------------------------
__device__ __forceinline__ uint32_t smem_u32(const void* p) {
    uint32_t a;
    asm("{ .reg .u64 t; cvta.to.shared.u64 t, %1; cvt.u32.u64 %0, t; }" : "=r"(a) : "l"(p));
    return a;
}
__device__ __forceinline__ float tf32r(float x) {
    uint32_t u;
    asm("cvt.rna.tf32.f32 %0, %1;" : "=r"(u) : "f"(x));
    return __uint_as_float(u);
}
#define CP_ASYNC16(dst, src) \
    asm volatile("cp.async.cg.shared.global [%0], [%1], 16;" :: "r"(dst), "l"(src) : "memory")
#define CP_COMMIT() asm volatile("cp.async.commit_group;" ::: "memory")
#define CP_WAIT1()  asm volatile("cp.async.wait_group 1;" ::: "memory")
#define CP_WAIT0()  asm volatile("cp.async.wait_group 0;" ::: "memory")

#define MMA_TF32(c, a, b) \
    asm volatile("mma.sync.aligned.m16n8k8.row.col.f32.tf32.tf32.f32 " \
        "{%0,%1,%2,%3}, {%4,%5,%6,%7}, {%8,%9}, {%0,%1,%2,%3};" \
        : "+f"((c)[0]), "+f"((c)[1]), "+f"((c)[2]), "+f"((c)[3]) \
        : "r"((a)[0]), "r"((a)[1]), "r"((a)[2]), "r"((a)[3]), "r"((b)[0]), "r"((b)[1]))

// ---------------------------------------------------------------------------
// tf32 GEMM (all-NT): C[M,N] = alpha * A[M,K] @ B[N,K]^T (+ bias[N])
// A,B stored with k-dim permuted by p8 ([k0,k4,k1,k5,k2,k6,k3,k7] per
// 8-block) so each fragment pair is one LDS.64. Smem rows are exactly 32
// floats; 16B chunks XOR-swizzled by (row&3)<<1 (conflict-free LDS.64 + no
// padding). BM=128 BN=128 BK=32, 256 thr = 8 warps (2M x 4N), warp 64x32.
// 3-stage cp.async, prefetch distance 2, one barrier/iter, 2 CTAs/SM.
// MODE 0: fp32 out (true cols). MODE 1: tf32-rounded out, cols p8-permuted.
// MODE 2: rounded + transposed (Vt[b][col][p8(tok)]).
// ---------------------------------------------------------------------------
#define BM 128
#define BN 128
#define BK 32
#define STG_FLOATS ((BM + BN) * 32)     // 8192
#define STG_BYTES  (STG_FLOATS * 4)     // 32768
#define GEMM_SMEM  (3 * STG_BYTES)      // 98304

template <int MODE, bool HAS_BIAS>
__global__ __launch_bounds__(256, 2)
void tf32_gemm(const float* __restrict__ A, const float* __restrict__ B,
               const float* __restrict__ bias, float* __restrict__ C,
               int M, int N, int K, float alpha,
               size_t sA, size_t sB, size_t sC)
{
    extern __shared__ float sm[];
    const uint32_t sb = smem_u32(sm);

    const int tid  = threadIdx.x;
    const int wid  = tid >> 5, lane = tid & 31;
    const int g    = lane >> 2, t4 = lane & 3;
    const int wm   = wid & 1,  wn = wid >> 1;

    const int m0 = blockIdx.y * BM;
    const int n0 = blockIdx.x * BN;
    A += (size_t)blockIdx.z * sA + (size_t)m0 * K;
    B += (size_t)blockIdx.z * sB + (size_t)n0 * K;

    auto load_stage = [&](int kt, int s) {
        const uint32_t st = sb + s * STG_BYTES;
        const int k0 = kt * BK;
#pragma unroll
        for (int i = 0; i < 4; i++) {          // A: 128 rows x 8 chunks of 16B
            int id = tid + i * 256, r = id >> 3, c = id & 7;
            CP_ASYNC16(st + r * 128 + ((c ^ ((r & 3) << 1)) * 16),
                       A + (size_t)r * K + k0 + c * 4);
        }
#pragma unroll
        for (int i = 0; i < 4; i++) {          // B: 128 rows x 8 chunks
            int id = tid + i * 256, r = id >> 3, c = id & 7;
            CP_ASYNC16(st + BM * 128 + r * 128 + ((c ^ ((r & 3) << 1)) * 16),
                       B + (size_t)r * K + k0 + c * 4);
        }
        CP_COMMIT();
    };

    // fragment word offsets per ks (swizzle is row-invariant for this thread:
    // all rows it touches are == g mod 8)
    int off[4];
#pragma unroll
    for (int ks = 0; ks < 4; ks++)
        off[ks] = (((2 * ks + (t4 >> 1)) ^ ((g & 3) << 1)) << 2) | ((t4 & 1) << 1);

    const float* aBase = sm + (wm * 64 + g) * 32;
    const float* bBase = sm + BM * 32 + (wn * 32 + g) * 32;

    float acc[4][4][4];
#pragma unroll
    for (int mi = 0; mi < 4; mi++)
#pragma unroll
        for (int ni = 0; ni < 4; ni++)
#pragma unroll
            for (int r = 0; r < 4; r++) acc[mi][ni][r] = 0.0f;

    const int KT = K / BK;
    load_stage(0, 0);
    load_stage(1, 1);

    for (int kt = 0; kt < KT; kt++) {
        if (kt + 1 < KT) { CP_WAIT1(); } else { CP_WAIT0(); }
        __syncthreads();
        // stage (kt+2)%3 == stage of kt-1, whose reads finished before the
        // barrier above -> safe to refill now, overlapping compute of kt.
        if (kt + 2 < KT) load_stage(kt + 2, (kt + 2) % 3);

        const float* As = aBase + (kt % 3) * STG_FLOATS;
        const float* Bs = bBase + (kt % 3) * STG_FLOATS;

#pragma unroll
        for (int ks = 0; ks < 4; ks++) {
            uint32_t af[4][4], bf[4][2];
#pragma unroll
            for (int mi = 0; mi < 4; mi++) {
                float2 lo = *reinterpret_cast<const float2*>(As + mi * 16 * 32 + off[ks]);
                float2 hi = *reinterpret_cast<const float2*>(As + mi * 16 * 32 + 8 * 32 + off[ks]);
                af[mi][0] = __float_as_uint(lo.x);
                af[mi][1] = __float_as_uint(hi.x);
                af[mi][2] = __float_as_uint(lo.y);
                af[mi][3] = __float_as_uint(hi.y);
            }
#pragma unroll
            for (int ni = 0; ni < 4; ni++) {
                float2 b = *reinterpret_cast<const float2*>(Bs + ni * 8 * 32 + off[ks]);
                bf[ni][0] = __float_as_uint(b.x);
                bf[ni][1] = __float_as_uint(b.y);
            }
#pragma unroll
            for (int mi = 0; mi < 4; mi++)
#pragma unroll
                for (int ni = 0; ni < 4; ni++)
                    MMA_TF32(acc[mi][ni], af[mi], bf[ni]);
        }
    }

    // ---- epilogue ----
    if (MODE == 2) {
        // transposed + rounded: Vt[b][col][p8(tok)]
        float* Cb = C + (size_t)(m0 / TSEQ) * EMB * TSEQ;
        const int pg = ((g & 3) << 1) | (g >> 2);
        const int tokbase = (m0 % TSEQ) + wm * 64 + pg;
#pragma unroll
        for (int mi = 0; mi < 4; mi++) {
            const int tok = tokbase + mi * 16;
#pragma unroll
            for (int ni = 0; ni < 4; ni++) {
                const int col = n0 + wn * 32 + ni * 8 + t4 * 2;
                float b0 = HAS_BIAS ? __ldg(bias + col)     : 0.0f;
                float b1 = HAS_BIAS ? __ldg(bias + col + 1) : 0.0f;
                Cb[(size_t)col * TSEQ + tok]           = tf32r(acc[mi][ni][0] * alpha + b0);
                Cb[(size_t)(col + 1) * TSEQ + tok]     = tf32r(acc[mi][ni][1] * alpha + b1);
                Cb[(size_t)col * TSEQ + tok + 8]       = tf32r(acc[mi][ni][2] * alpha + b0);
                Cb[(size_t)(col + 1) * TSEQ + tok + 8] = tf32r(acc[mi][ni][3] * alpha + b1);
            }
        }
    } else if (MODE == 1) {
        // rounded out, columns stored p8-permuted (they are a k-dim downstream)
        C += (size_t)blockIdx.z * sC;
        const int q0 = ((2 * t4 & 3) << 1) | ((2 * t4) >> 2);
        const int q1 = (((2 * t4 + 1) & 3) << 1) | ((2 * t4 + 1) >> 2);
#pragma unroll
        for (int mi = 0; mi < 4; mi++) {
            const int row = m0 + wm * 64 + mi * 16 + g;
#pragma unroll
            for (int ni = 0; ni < 4; ni++) {
                const int colb = n0 + wn * 32 + ni * 8;
                float b0 = HAS_BIAS ? __ldg(bias + colb + 2 * t4)     : 0.0f;
                float b1 = HAS_BIAS ? __ldg(bias + colb + 2 * t4 + 1) : 0.0f;
                C[(size_t)row * N + colb + q0]       = tf32r(acc[mi][ni][0] * alpha + b0);
                C[(size_t)row * N + colb + q1]       = tf32r(acc[mi][ni][1] * alpha + b1);
                C[(size_t)(row + 8) * N + colb + q0] = tf32r(acc[mi][ni][2] * alpha + b0);
                C[(size_t)(row + 8) * N + colb + q1] = tf32r(acc[mi][ni][3] * alpha + b1);
            }
        }
    } else {
        // MODE 0: plain fp32, true column order
        C += (size_t)blockIdx.z * sC;
#pragma unroll
        for (int mi = 0; mi < 4; mi++) {
            const int row = m0 + wm * 64 + mi * 16 + g;
#pragma unroll
            for (int ni = 0; ni < 4; ni++) {
                const int col = n0 + wn * 32 + ni * 8 + t4 * 2;
                float b0 = HAS_BIAS ? __ldg(bias + col)     : 0.0f;
                float b1 = HAS_BIAS ? __ldg(bias + col + 1) : 0.0f;
                float f0 = acc[mi][ni][0] * alpha + b0;
                float f1 = acc[mi][ni][1] * alpha + b1;
                float f2 = acc[mi][ni][2] * alpha + b0;
                float f3 = acc[mi][ni][3] * alpha + b1;
                *reinterpret_cast<float2*>(C + (size_t)row * N + col)       = make_float2(f0, f1);
                *reinterpret_cast<float2*>(C + (size_t)(row + 8) * N + col) = make_float2(f2, f3);
            }
        }
    }
}

// ---------------------------------------------------------------------------
// rounding passes: tf32-round AND k-permute (8 elements per thread)
// out positions within 8-block: [e0,e4,e1,e5,e2,e6,e3,e7]
// ---------------------------------------------------------------------------
__device__ __forceinline__ void round_perm8(float4 i0, float4 i1,
                                            float4& o0, float4& o1)
{
    o0 = make_float4(tf32r(i0.x), tf32r(i1.x), tf32r(i0.y), tf32r(i1.y));
    o1 = make_float4(tf32r(i0.z), tf32r(i1.z), tf32r(i0.w), tf32r(i1.w));
}

__global__ void round_act_kernel(const float4* __restrict__ a, float4* __restrict__ ya,
                                 const float4* __restrict__ b, float4* __restrict__ yb,
                                 int n8)
{
    int i = blockIdx.x * blockDim.x + threadIdx.x;
    if (i >= n8) return;
    const float4* x = blockIdx.y ? b : a;
    float4*       y = blockIdx.y ? yb : ya;
    float4 o0, o1;
    round_perm8(x[2 * i], x[2 * i + 1], o0, o1);
    y[2 * i] = o0; y[2 * i + 1] = o1;
}

__global__ void round_w_kernel(const float4* __restrict__ w0, const float4* __restrict__ w1,
                               const float4* __restrict__ w2, const float4* __restrict__ w3,
                               float4* __restrict__ y, int n8)
{
    int i = blockIdx.x * blockDim.x + threadIdx.x;
    if (i >= n8) return;
    const float4* src = (blockIdx.y == 0) ? w0 : (blockIdx.y == 1) ? w1
                      : (blockIdx.y == 2) ? w2 : w3;
    float4 o0, o1;
    round_perm8(src[2 * i], src[2 * i + 1], o0, o1);
    y[(size_t)blockIdx.y * 2 * n8 + 2 * i]     = o0;
    y[(size_t)blockIdx.y * 2 * n8 + 2 * i + 1] = o1;
}

// ---------------------------------------------------------------------------
// softmax over 2048-length rows (in place): reads true-order S, writes
// tf32-rounded P with k-permuted columns. 8 elements per thread.
// ---------------------------------------------------------------------------
__device__ __forceinline__ float blk_red_max(float v) {
    __shared__ float sh[8]; __shared__ float res;
    const int lane = threadIdx.x & 31, warp = threadIdx.x >> 5;
#pragma unroll
    for (int o = 16; o > 0; o >>= 1) v = fmaxf(v, __shfl_xor_sync(0xffffffffu, v, o));
    if (lane == 0) sh[warp] = v;
    __syncthreads();
    if (warp == 0) {
        float w = (lane < 8) ? sh[lane] : -3.0e38f;
#pragma unroll
        for (int o = 4; o > 0; o >>= 1) w = fmaxf(w, __shfl_xor_sync(0xffffffffu, w, o));
        if (lane == 0) res = w;
    }
    __syncthreads();
    return res;
}
__device__ __forceinline__ float blk_red_sum(float v) {
    __shared__ float sh[8]; __shared__ float res;
    const int lane = threadIdx.x & 31, warp = threadIdx.x >> 5;
#pragma unroll
    for (int o = 16; o > 0; o >>= 1) v += __shfl_xor_sync(0xffffffffu, v, o);
    if (lane == 0) sh[warp] = v;
    __syncthreads();
    if (warp == 0) {
        float w = (lane < 8) ? sh[lane] : 0.0f;
#pragma unroll
        for (int o = 4; o > 0; o >>= 1) w += __shfl_xor_sync(0xffffffffu, w, o);
        if (lane == 0) res = w;
    }
    __syncthreads();
    return res;
}

__global__ __launch_bounds__(256)
void softmax_kernel(float* __restrict__ S)
{
    float4* row = reinterpret_cast<float4*>(S + (size_t)blockIdx.x * TSEQ);
    const int t = threadIdx.x;

    float4 v0 = row[2 * t];       // elements 8t .. 8t+3
    float4 v1 = row[2 * t + 1];   // elements 8t+4 .. 8t+7

    float mx = fmaxf(fmaxf(fmaxf(v0.x, v0.y), fmaxf(v0.z, v0.w)),
                     fmaxf(fmaxf(v1.x, v1.y), fmaxf(v1.z, v1.w)));
    mx = blk_red_max(mx);

    v0.x = __expf(v0.x - mx); v0.y = __expf(v0.y - mx);
    v0.z = __expf(v0.z - mx); v0.w = __expf(v0.w - mx);
    v1.x = __expf(v1.x - mx); v1.y = __expf(v1.y - mx);
    v1.z = __expf(v1.z - mx); v1.w = __expf(v1.w - mx);

    float s = (v0.x + v0.y + v0.z + v0.w) + (v1.x + v1.y + v1.z + v1.w);
    s = blk_red_sum(s);
    const float inv = 1.0f / s;

    v0.x *= inv; v0.y *= inv; v0.z *= inv; v0.w *= inv;
    v1.x *= inv; v1.y *= inv; v1.z *= inv; v1.w *= inv;

    float4 o0, o1;
    round_perm8(v0, v1, o0, o1);
    row[2 * t]     = o0;
    row[2 * t + 1] = o1;
}

// ---------------------------------------------------------------------------
extern "C" void kernel_launch(void* const* d_in, const int* in_sizes, int n_in,
                              void* d_out, int out_size)
{
    const float* target = (const float*)d_in[0];
    const float* source = (const float*)d_in[1];
    const float* Wq = (const float*)d_in[2];
    const float* bq = (const float*)d_in[3];
    const float* Wk = (const float*)d_in[4];
    const float* bk = (const float*)d_in[5];
    const float* Wv = (const float*)d_in[6];
    const float* bv = (const float*)d_in[7];
    const float* Wo = (const float*)d_in[8];
    const float* bo = (const float*)d_in[9];
    float* out = (float*)d_out;

    float *T, *Src, *W, *Q, *Kb, *Vt, *S, *O;
    cudaGetSymbolAddress((void**)&T,   g_T);
    cudaGetSymbolAddress((void**)&Src, g_Src);
    cudaGetSymbolAddress((void**)&W,   g_W);
    cudaGetSymbolAddress((void**)&Q,   g_Q);
    cudaGetSymbolAddress((void**)&Kb,  g_K);
    cudaGetSymbolAddress((void**)&Vt,  g_Vt);
    cudaGetSymbolAddress((void**)&S,   g_S);
    cudaGetSymbolAddress((void**)&O,   g_O);

    cudaFuncSetAttribute(tf32_gemm<0, false>, cudaFuncAttributeMaxDynamicSharedMemorySize, GEMM_SMEM);
    cudaFuncSetAttribute(tf32_gemm<0, true>,  cudaFuncAttributeMaxDynamicSharedMemorySize, GEMM_SMEM);
    cudaFuncSetAttribute(tf32_gemm<1, false>, cudaFuncAttributeMaxDynamicSharedMemorySize, GEMM_SMEM);
    cudaFuncSetAttribute(tf32_gemm<1, true>,  cudaFuncAttributeMaxDynamicSharedMemorySize, GEMM_SMEM);
    cudaFuncSetAttribute(tf32_gemm<2, true>,  cudaFuncAttributeMaxDynamicSharedMemorySize, GEMM_SMEM);

    // launch 0: round+perm both activations; launch 1: round+perm 4 weights
    {
        dim3 ga((unsigned)(NELEM / 8 / 256), 2, 1);
        round_act_kernel<<<ga, 256>>>((const float4*)target, (float4*)T,
                                      (const float4*)source, (float4*)Src,
                                      (int)(NELEM / 8));
        dim3 gw((unsigned)(EMB * EMB / 8 / 256), 4, 1);
        round_w_kernel<<<gw, 256>>>((const float4*)Wq, (const float4*)Wk,
                                    (const float4*)Wv, (const float4*)Wo,
                                    (float4*)W, EMB * EMB / 8);
    }

    const float scale = 1.0f / 32.0f;  // 1/sqrt(1024)

    // launches 2-4: projections
    {
        dim3 grd(EMB / BN, MTOT / BM, 1);
        tf32_gemm<1, true><<<grd, 256, GEMM_SMEM>>>(T,   W + 0u * EMB * EMB, bq, Q,
                                                    MTOT, EMB, EMB, 1.0f, 0, 0, 0);
        tf32_gemm<1, true><<<grd, 256, GEMM_SMEM>>>(Src, W + 1u * EMB * EMB, bk, Kb,
                                                    MTOT, EMB, EMB, 1.0f, 0, 0, 0);
        tf32_gemm<2, true><<<grd, 256, GEMM_SMEM>>>(Src, W + 2u * EMB * EMB, bv, Vt,
                                                    MTOT, EMB, EMB, 1.0f, 0, 0, 0);
    }

    // launch 5 (ncu -s 5 -c 1 captures this): S = Q @ K^T / 32
    {
        dim3 grd(TSEQ / BN, TSEQ / BM, BATCH);
        tf32_gemm<0, false><<<grd, 256, GEMM_SMEM>>>(Q, Kb, nullptr, S,
            TSEQ, TSEQ, EMB, scale,
            (size_t)TSEQ * EMB, (size_t)TSEQ * EMB, (size_t)TSEQ * TSEQ);
    }

    // P = softmax(S) in place (rounded + k-permuted)
    softmax_kernel<<<BATCH * TSEQ, 256>>>(S);

    // O = P @ Vt^T (batched, K=2048)
    {
        dim3 grd(EMB / BN, TSEQ / BM, BATCH);
        tf32_gemm<1, false><<<grd, 256, GEMM_SMEM>>>(S, Vt, nullptr, O,
            TSEQ, EMB, TSEQ, 1.0f,
            (size_t)TSEQ * TSEQ, (size_t)EMB * TSEQ, (size_t)TSEQ * EMB);
    }

    // out = O @ Wo^T + bo (fp32, true order)
    {
        dim3 grd(EMB / BN, MTOT / BM, 1);
        tf32_gemm<0, true><<<grd, 256, GEMM_SMEM>>>(O, W + 3u * EMB * EMB, bo, out,
                                                    MTOT, EMB, EMB, 1.0f, 0, 0, 0);
    }
}

// round 13
// speedup vs baseline: 1.1323x; 1.0120x over previous
#include <cuda_runtime.h>
#include <cstdint>

// Cross attention B=8, Tq=Tk=2048, D=1024, fp32.
// All 6 GEMMs via mma.sync m16n8k8 tf32. K-dim stored PERMUTED (p8) so
// fragment loads are LDS.64. 128x128 tiles, 2 CTAs/SM, XOR-swizzled smem,
// 3-stage cp.async pipeline. Q/K/V projections fused into ONE launch.

#define BATCH 8
#define TSEQ  2048
#define EMB   1024
#define MTOT  (BATCH * TSEQ)          // 16384
#define NELEM ((size_t)MTOT * EMB)    // 16M

// ---------------- scratch (__device__ globals; no allocation) --------------
__device__ float g_T[NELEM];
__device__ float g_Src[NELEM];
__device__ float g_W[4u * EMB * EMB];
__device__ float g_Q[NELEM];
__device__ float g_K[NELEM];
__device__ float g_Vt[NELEM];                        // [B][EMB][TSEQ]
__device__ float g_S[(size_t)BATCH * TSEQ * TSEQ];   // scores -> P in place
__device__ float g_O[NELEM];

// ---------------- helpers --------------------------------------------------
__device__ __forceinline__ uint32_t smem_u32(const void* p) {
    uint32_t a;
    asm("{ .reg .u64 t; cvta.to.shared.u64 t, %1; cvt.u32.u64 %0, t; }" : "=r"(a) : "l"(p));
    return a;
}
__device__ __forceinline__ float tf32r(float x) {
    uint32_t u;
    asm("cvt.rna.tf32.f32 %0, %1;" : "=r"(u) : "f"(x));
    return __uint_as_float(u);
}
#define CP_ASYNC16(dst, src) \
    asm volatile("cp.async.cg.shared.global [%0], [%1], 16;" :: "r"(dst), "l"(src) : "memory")
#define CP_COMMIT() asm volatile("cp.async.commit_group;" ::: "memory")
#define CP_WAIT1()  asm volatile("cp.async.wait_group 1;" ::: "memory")
#define CP_WAIT0()  asm volatile("cp.async.wait_group 0;" ::: "memory")

#define MMA_TF32(c, a, b) \
    asm volatile("mma.sync.aligned.m16n8k8.row.col.f32.tf32.tf32.f32 " \
        "{%0,%1,%2,%3}, {%4,%5,%6,%7}, {%8,%9}, {%0,%1,%2,%3};" \
        : "+f"((c)[0]), "+f"((c)[1]), "+f"((c)[2]), "+f"((c)[3]) \
        : "r"((a)[0]), "r"((a)[1]), "r"((a)[2]), "r"((a)[3]), "r"((b)[0]), "r"((b)[1]))

#define BM 128
#define BN 128
#define BK 32
#define STG_FLOATS ((BM + BN) * 32)     // 8192
#define STG_BYTES  (STG_FLOATS * 4)     // 32768
#define GEMM_SMEM  (3 * STG_BYTES)      // 98304

// ---------------------------------------------------------------------------
// Shared mainloop: acc += A[m0:m0+128, :K] @ B[n0:n0+128, :K]^T
// (A,B pre-offset to their tile rows; both k-p8-permuted in gmem)
// ---------------------------------------------------------------------------
__device__ __forceinline__ void tf32_mainloop(
    const float* __restrict__ A, const float* __restrict__ B,
    int K, float* sm, uint32_t sb, int tid, float acc[4][4][4])
{
    const int wid  = tid >> 5, lane = tid & 31;
    const int g    = lane >> 2, t4 = lane & 3;
    const int wm   = wid & 1,  wn = wid >> 1;

    auto load_stage = [&](int kt, int s) {
        const uint32_t st = sb + s * STG_BYTES;
        const int k0 = kt * BK;
#pragma unroll
        for (int i = 0; i < 4; i++) {          // A: 128 rows x 8 chunks of 16B
            int id = tid + i * 256, r = id >> 3, c = id & 7;
            CP_ASYNC16(st + r * 128 + ((c ^ ((r & 3) << 1)) * 16),
                       A + (size_t)r * K + k0 + c * 4);
        }
#pragma unroll
        for (int i = 0; i < 4; i++) {          // B: 128 rows x 8 chunks
            int id = tid + i * 256, r = id >> 3, c = id & 7;
            CP_ASYNC16(st + BM * 128 + r * 128 + ((c ^ ((r & 3) << 1)) * 16),
                       B + (size_t)r * K + k0 + c * 4);
        }
        CP_COMMIT();
    };

    int off[4];
#pragma unroll
    for (int ks = 0; ks < 4; ks++)
        off[ks] = (((2 * ks + (t4 >> 1)) ^ ((g & 3) << 1)) << 2) | ((t4 & 1) << 1);

    const float* aBase = sm + (wm * 64 + g) * 32;
    const float* bBase = sm + BM * 32 + (wn * 32 + g) * 32;

    const int KT = K / BK;
    load_stage(0, 0);
    load_stage(1, 1);

    for (int kt = 0; kt < KT; kt++) {
        if (kt + 1 < KT) { CP_WAIT1(); } else { CP_WAIT0(); }
        __syncthreads();
        if (kt + 2 < KT) load_stage(kt + 2, (kt + 2) % 3);

        const float* As = aBase + (kt % 3) * STG_FLOATS;
        const float* Bs = bBase + (kt % 3) * STG_FLOATS;

#pragma unroll
        for (int ks = 0; ks < 4; ks++) {
            uint32_t af[4][4], bf[4][2];
#pragma unroll
            for (int mi = 0; mi < 4; mi++) {
                float2 lo = *reinterpret_cast<const float2*>(As + mi * 16 * 32 + off[ks]);
                float2 hi = *reinterpret_cast<const float2*>(As + mi * 16 * 32 + 8 * 32 + off[ks]);
                af[mi][0] = __float_as_uint(lo.x);
                af[mi][1] = __float_as_uint(hi.x);
                af[mi][2] = __float_as_uint(lo.y);
                af[mi][3] = __float_as_uint(hi.y);
            }
#pragma unroll
            for (int ni = 0; ni < 4; ni++) {
                float2 b = *reinterpret_cast<const float2*>(Bs + ni * 8 * 32 + off[ks]);
                bf[ni][0] = __float_as_uint(b.x);
                bf[ni][1] = __float_as_uint(b.y);
            }
#pragma unroll
            for (int mi = 0; mi < 4; mi++)
#pragma unroll
                for (int ni = 0; ni < 4; ni++)
                    MMA_TF32(acc[mi][ni], af[mi], bf[ni]);
        }
    }
}

// ---- epilogue helpers ------------------------------------------------------
// MODE1: tf32-rounded, columns p8-permuted (output is a k-dim downstream)
__device__ __forceinline__ void epi_mode1(
    float acc[4][4][4], float* __restrict__ C, const float* __restrict__ bias,
    int m0, int n0, int N, float alpha, int tid, bool has_bias)
{
    const int wid = tid >> 5, lane = tid & 31;
    const int g = lane >> 2, t4 = lane & 3;
    const int wm = wid & 1, wn = wid >> 1;
    const int q0 = ((2 * t4 & 3) << 1) | ((2 * t4) >> 2);
    const int q1 = (((2 * t4 + 1) & 3) << 1) | ((2 * t4 + 1) >> 2);
#pragma unroll
    for (int mi = 0; mi < 4; mi++) {
        const int row = m0 + wm * 64 + mi * 16 + g;
#pragma unroll
        for (int ni = 0; ni < 4; ni++) {
            const int colb = n0 + wn * 32 + ni * 8;
            float b0 = has_bias ? __ldg(bias + colb + 2 * t4)     : 0.0f;
            float b1 = has_bias ? __ldg(bias + colb + 2 * t4 + 1) : 0.0f;
            C[(size_t)row * N + colb + q0]       = tf32r(acc[mi][ni][0] * alpha + b0);
            C[(size_t)row * N + colb + q1]       = tf32r(acc[mi][ni][1] * alpha + b1);
            C[(size_t)(row + 8) * N + colb + q0] = tf32r(acc[mi][ni][2] * alpha + b0);
            C[(size_t)(row + 8) * N + colb + q1] = tf32r(acc[mi][ni][3] * alpha + b1);
        }
    }
}

// MODE2: rounded + transposed -> Vt[b][col][p8(tok)]
__device__ __forceinline__ void epi_mode2(
    float acc[4][4][4], float* __restrict__ Cb, const float* __restrict__ bias,
    int m0, int n0, int tid)
{
    const int wid = tid >> 5, lane = tid & 31;
    const int g = lane >> 2, t4 = lane & 3;
    const int wm = wid & 1, wn = wid >> 1;
    const int pg = ((g & 3) << 1) | (g >> 2);
    const int tokbase = (m0 % TSEQ) + wm * 64 + pg;
#pragma unroll
    for (int mi = 0; mi < 4; mi++) {
        const int tok = tokbase + mi * 16;
#pragma unroll
        for (int ni = 0; ni < 4; ni++) {
            const int col = n0 + wn * 32 + ni * 8 + t4 * 2;
            float b0 = __ldg(bias + col);
            float b1 = __ldg(bias + col + 1);
            Cb[(size_t)col * TSEQ + tok]           = tf32r(acc[mi][ni][0] + b0);
            Cb[(size_t)(col + 1) * TSEQ + tok]     = tf32r(acc[mi][ni][1] + b1);
            Cb[(size_t)col * TSEQ + tok + 8]       = tf32r(acc[mi][ni][2] + b0);
            Cb[(size_t)(col + 1) * TSEQ + tok + 8] = tf32r(acc[mi][ni][3] + b1);
        }
    }
}

// ---------------------------------------------------------------------------
// Generic GEMM kernel (MODE 0: plain fp32 out; MODE 1: rounded+permuted out)
// ---------------------------------------------------------------------------
template <int MODE, bool HAS_BIAS>
__global__ __launch_bounds__(256, 2)
void tf32_gemm(const float* __restrict__ A, const float* __restrict__ B,
               const float* __restrict__ bias, float* __restrict__ C,
               int M, int N, int K, float alpha,
               size_t sA, size_t sB, size_t sC)
{
    extern __shared__ float sm[];
    const uint32_t sb = smem_u32(sm);
    const int tid = threadIdx.x;

    const int m0 = blockIdx.y * BM;
    const int n0 = blockIdx.x * BN;
    A += (size_t)blockIdx.z * sA + (size_t)m0 * K;
    B += (size_t)blockIdx.z * sB + (size_t)n0 * K;

    float acc[4][4][4];
#pragma unroll
    for (int mi = 0; mi < 4; mi++)
#pragma unroll
        for (int ni = 0; ni < 4; ni++)
#pragma unroll
            for (int r = 0; r < 4; r++) acc[mi][ni][r] = 0.0f;

    tf32_mainloop(A, B, K, sm, sb, tid, acc);

    C += (size_t)blockIdx.z * sC;
    if (MODE == 1) {
        epi_mode1(acc, C, bias, m0, n0, N, alpha, tid, HAS_BIAS);
    } else {
        const int wid = tid >> 5, lane = tid & 31;
        const int g = lane >> 2, t4 = lane & 3;
        const int wm = wid & 1, wn = wid >> 1;
#pragma unroll
        for (int mi = 0; mi < 4; mi++) {
            const int row = m0 + wm * 64 + mi * 16 + g;
#pragma unroll
            for (int ni = 0; ni < 4; ni++) {
                const int col = n0 + wn * 32 + ni * 8 + t4 * 2;
                float b0 = HAS_BIAS ? __ldg(bias + col)     : 0.0f;
                float b1 = HAS_BIAS ? __ldg(bias + col + 1) : 0.0f;
                float f0 = acc[mi][ni][0] * alpha + b0;
                float f1 = acc[mi][ni][1] * alpha + b1;
                float f2 = acc[mi][ni][2] * alpha + b0;
                float f3 = acc[mi][ni][3] * alpha + b1;
                *reinterpret_cast<float2*>(C + (size_t)row * N + col)       = make_float2(f0, f1);
                *reinterpret_cast<float2*>(C + (size_t)(row + 8) * N + col) = make_float2(f2, f3);
            }
        }
    }
}

// ---------------------------------------------------------------------------
// Fused Q/K/V projection: one launch, 3 segments along grid.x.
// seg 0: Q = T@Wq^T+bq (MODE1)  seg 1: K = Src@Wk^T+bk (MODE1)
// seg 2: Vt = (Src@Wv^T+bv)^T per batch (MODE2)
// ---------------------------------------------------------------------------
__global__ __launch_bounds__(256, 2)
void proj_fused(const float* __restrict__ T, const float* __restrict__ Src,
                const float* __restrict__ W,
                const float* __restrict__ bq, const float* __restrict__ bk,
                const float* __restrict__ bv,
                float* __restrict__ Q, float* __restrict__ Kb,
                float* __restrict__ Vt)
{
    extern __shared__ float sm[];
    const uint32_t sb = smem_u32(sm);
    const int tid = threadIdx.x;

    const int seg = blockIdx.x >> 3;             // EMB/BN = 8 tiles per segment
    const int n0  = (blockIdx.x & 7) * BN;
    const int m0  = blockIdx.y * BM;

    const float* A = (seg == 0) ? T : Src;
    const float* B = W + (size_t)seg * EMB * EMB;
    A += (size_t)m0 * EMB;
    B += (size_t)n0 * EMB;

    float acc[4][4][4];
#pragma unroll
    for (int mi = 0; mi < 4; mi++)
#pragma unroll
        for (int ni = 0; ni < 4; ni++)
#pragma unroll
            for (int r = 0; r < 4; r++) acc[mi][ni][r] = 0.0f;

    tf32_mainloop(A, B, EMB, sm, sb, tid, acc);

    if (seg == 0) {
        epi_mode1(acc, Q, bq, m0, n0, EMB, 1.0f, tid, true);
    } else if (seg == 1) {
        epi_mode1(acc, Kb, bk, m0, n0, EMB, 1.0f, tid, true);
    } else {
        float* Cb = Vt + (size_t)(m0 / TSEQ) * EMB * TSEQ;
        epi_mode2(acc, Cb, bv, m0, n0, tid);
    }
}

// ---------------------------------------------------------------------------
// rounding passes: tf32-round AND k-permute (8 elements per thread)
// ---------------------------------------------------------------------------
__device__ __forceinline__ void round_perm8(float4 i0, float4 i1,
                                            float4& o0, float4& o1)
{
    o0 = make_float4(tf32r(i0.x), tf32r(i1.x), tf32r(i0.y), tf32r(i1.y));
    o1 = make_float4(tf32r(i0.z), tf32r(i1.z), tf32r(i0.w), tf32r(i1.w));
}

__global__ void round_act_kernel(const float4* __restrict__ a, float4* __restrict__ ya,
                                 const float4* __restrict__ b, float4* __restrict__ yb,
                                 int n8)
{
    int i = blockIdx.x * blockDim.x + threadIdx.x;
    if (i >= n8) return;
    const float4* x = blockIdx.y ? b : a;
    float4*       y = blockIdx.y ? yb : ya;
    float4 o0, o1;
    round_perm8(x[2 * i], x[2 * i + 1], o0, o1);
    y[2 * i] = o0; y[2 * i + 1] = o1;
}

__global__ void round_w_kernel(const float4* __restrict__ w0, const float4* __restrict__ w1,
                               const float4* __restrict__ w2, const float4* __restrict__ w3,
                               float4* __restrict__ y, int n8)
{
    int i = blockIdx.x * blockDim.x + threadIdx.x;
    if (i >= n8) return;
    const float4* src = (blockIdx.y == 0) ? w0 : (blockIdx.y == 1) ? w1
                      : (blockIdx.y == 2) ? w2 : w3;
    float4 o0, o1;
    round_perm8(src[2 * i], src[2 * i + 1], o0, o1);
    y[(size_t)blockIdx.y * 2 * n8 + 2 * i]     = o0;
    y[(size_t)blockIdx.y * 2 * n8 + 2 * i + 1] = o1;
}

// ---------------------------------------------------------------------------
// softmax over 2048-length rows (in place): reads true-order S, writes
// tf32-rounded P with k-permuted columns. 8 elements per thread.
// ---------------------------------------------------------------------------
__device__ __forceinline__ float blk_red_max(float v) {
    __shared__ float sh[8]; __shared__ float res;
    const int lane = threadIdx.x & 31, warp = threadIdx.x >> 5;
#pragma unroll
    for (int o = 16; o > 0; o >>= 1) v = fmaxf(v, __shfl_xor_sync(0xffffffffu, v, o));
    if (lane == 0) sh[warp] = v;
    __syncthreads();
    if (warp == 0) {
        float w = (lane < 8) ? sh[lane] : -3.0e38f;
#pragma unroll
        for (int o = 4; o > 0; o >>= 1) w = fmaxf(w, __shfl_xor_sync(0xffffffffu, w, o));
        if (lane == 0) res = w;
    }
    __syncthreads();
    return res;
}
__device__ __forceinline__ float blk_red_sum(float v) {
    __shared__ float sh[8]; __shared__ float res;
    const int lane = threadIdx.x & 31, warp = threadIdx.x >> 5;
#pragma unroll
    for (int o = 16; o > 0; o >>= 1) v += __shfl_xor_sync(0xffffffffu, v, o);
    if (lane == 0) sh[warp] = v;
    __syncthreads();
    if (warp == 0) {
        float w = (lane < 8) ? sh[lane] : 0.0f;
#pragma unroll
        for (int o = 4; o > 0; o >>= 1) w += __shfl_xor_sync(0xffffffffu, w, o);
        if (lane == 0) res = w;
    }
    __syncthreads();
    return res;
}

__global__ __launch_bounds__(256)
void softmax_kernel(float* __restrict__ S)
{
    float4* row = reinterpret_cast<float4*>(S + (size_t)blockIdx.x * TSEQ);
    const int t = threadIdx.x;

    float4 v0 = row[2 * t];
    float4 v1 = row[2 * t + 1];

    float mx = fmaxf(fmaxf(fmaxf(v0.x, v0.y), fmaxf(v0.z, v0.w)),
                     fmaxf(fmaxf(v1.x, v1.y), fmaxf(v1.z, v1.w)));
    mx = blk_red_max(mx);

    v0.x = __expf(v0.x - mx); v0.y = __expf(v0.y - mx);
    v0.z = __expf(v0.z - mx); v0.w = __expf(v0.w - mx);
    v1.x = __expf(v1.x - mx); v1.y = __expf(v1.y - mx);
    v1.z = __expf(v1.z - mx); v1.w = __expf(v1.w - mx);

    float s = (v0.x + v0.y + v0.z + v0.w) + (v1.x + v1.y + v1.z + v1.w);
    s = blk_red_sum(s);
    const float inv = 1.0f / s;

    v0.x *= inv; v0.y *= inv; v0.z *= inv; v0.w *= inv;
    v1.x *= inv; v1.y *= inv; v1.z *= inv; v1.w *= inv;

    float4 o0, o1;
    round_perm8(v0, v1, o0, o1);
    row[2 * t]     = o0;
    row[2 * t + 1] = o1;
}

// ---------------------------------------------------------------------------
extern "C" void kernel_launch(void* const* d_in, const int* in_sizes, int n_in,
                              void* d_out, int out_size)
{
    const float* target = (const float*)d_in[0];
    const float* source = (const float*)d_in[1];
    const float* Wq = (const float*)d_in[2];
    const float* bq = (const float*)d_in[3];
    const float* Wk = (const float*)d_in[4];
    const float* bk = (const float*)d_in[5];
    const float* Wv = (const float*)d_in[6];
    const float* bv = (const float*)d_in[7];
    const float* Wo = (const float*)d_in[8];
    const float* bo = (const float*)d_in[9];
    float* out = (float*)d_out;

    float *T, *Src, *W, *Q, *Kb, *Vt, *S, *O;
    cudaGetSymbolAddress((void**)&T,   g_T);
    cudaGetSymbolAddress((void**)&Src, g_Src);
    cudaGetSymbolAddress((void**)&W,   g_W);
    cudaGetSymbolAddress((void**)&Q,   g_Q);
    cudaGetSymbolAddress((void**)&Kb,  g_K);
    cudaGetSymbolAddress((void**)&Vt,  g_Vt);
    cudaGetSymbolAddress((void**)&S,   g_S);
    cudaGetSymbolAddress((void**)&O,   g_O);

    cudaFuncSetAttribute(tf32_gemm<0, false>, cudaFuncAttributeMaxDynamicSharedMemorySize, GEMM_SMEM);
    cudaFuncSetAttribute(tf32_gemm<0, true>,  cudaFuncAttributeMaxDynamicSharedMemorySize, GEMM_SMEM);
    cudaFuncSetAttribute(tf32_gemm<1, false>, cudaFuncAttributeMaxDynamicSharedMemorySize, GEMM_SMEM);
    cudaFuncSetAttribute(proj_fused,          cudaFuncAttributeMaxDynamicSharedMemorySize, GEMM_SMEM);

    // launch 0-1: tf32-round + p8-permute inputs and weights
    {
        dim3 ga((unsigned)(NELEM / 8 / 256), 2, 1);
        round_act_kernel<<<ga, 256>>>((const float4*)target, (float4*)T,
                                      (const float4*)source, (float4*)Src,
                                      (int)(NELEM / 8));
        dim3 gw((unsigned)(EMB * EMB / 8 / 256), 4, 1);
        round_w_kernel<<<gw, 256>>>((const float4*)Wq, (const float4*)Wk,
                                    (const float4*)Wv, (const float4*)Wo,
                                    (float4*)W, EMB * EMB / 8);
    }

    const float scale = 1.0f / 32.0f;  // 1/sqrt(1024)

    // launch 2: fused Q/K/V projections (3 segments x 8 n-tiles, 128 m-tiles)
    {
        dim3 grd(24, MTOT / BM, 1);
        proj_fused<<<grd, 256, GEMM_SMEM>>>(T, Src, W, bq, bk, bv, Q, Kb, Vt);
    }

    // launch 3: S = Q @ K^T / 32 (batched)
    {
        dim3 grd(TSEQ / BN, TSEQ / BM, BATCH);
        tf32_gemm<0, false><<<grd, 256, GEMM_SMEM>>>(Q, Kb, nullptr, S,
            TSEQ, TSEQ, EMB, scale,
            (size_t)TSEQ * EMB, (size_t)TSEQ * EMB, (size_t)TSEQ * TSEQ);
    }

    // launch 4: P = softmax(S) in place (rounded + k-permuted)
    softmax_kernel<<<BATCH * TSEQ, 256>>>(S);

    // launch 5 (ncu -s 5 -c 1 captures this): O = P @ Vt^T (batched, K=2048)
    {
        dim3 grd(EMB / BN, TSEQ / BM, BATCH);
        tf32_gemm<1, false><<<grd, 256, GEMM_SMEM>>>(S, Vt, nullptr, O,
            TSEQ, EMB, TSEQ, 1.0f,
            (size_t)TSEQ * TSEQ, (size_t)EMB * TSEQ, (size_t)TSEQ * EMB);
    }

    // launch 6: out = O @ Wo^T + bo (fp32, true order)
    {
        dim3 grd(EMB / BN, MTOT / BM, 1);
        tf32_gemm<0, true><<<grd, 256, GEMM_SMEM>>>(O, W + 3u * EMB * EMB, bo, out,
                                                    MTOT, EMB, EMB, 1.0f, 0, 0, 0);
    }
}

// round 14
// speedup vs baseline: 1.1721x; 1.0351x over previous
#include <cuda_runtime.h>
#include <cstdint>

// Cross attention B=8, Tq=Tk=2048, D=1024, fp32.
// All 6 GEMMs via mma.sync m16n8k8 tf32. K-dim stored PERMUTED (p8) so
// fragment loads are LDS.64. 128x128 tiles, 2 CTAs/SM, XOR-swizzled smem,
// 3-stage cp.async pipeline, fragment DOUBLE-BUFFERING across ks steps.
// Q/K/V projections fused into one launch.

#define BATCH 8
#define TSEQ  2048
#define EMB   1024
#define MTOT  (BATCH * TSEQ)          // 16384
#define NELEM ((size_t)MTOT * EMB)    // 16M

// ---------------- scratch (__device__ globals; no allocation) --------------
__device__ float g_T[NELEM];
__device__ float g_Src[NELEM];
__device__ float g_W[4u * EMB * EMB];
__device__ float g_Q[NELEM];
__device__ float g_K[NELEM];
__device__ float g_Vt[NELEM];                        // [B][EMB][TSEQ]
__device__ float g_S[(size_t)BATCH * TSEQ * TSEQ];   // scores -> P in place
__device__ float g_O[NELEM];

// ---------------- helpers --------------------------------------------------
__device__ __forceinline__ uint32_t smem_u32(const void* p) {
    uint32_t a;
    asm("{ .reg .u64 t; cvta.to.shared.u64 t, %1; cvt.u32.u64 %0, t; }" : "=r"(a) : "l"(p));
    return a;
}
__device__ __forceinline__ float tf32r(float x) {
    uint32_t u;
    asm("cvt.rna.tf32.f32 %0, %1;" : "=r"(u) : "f"(x));
    return __uint_as_float(u);
}
#define CP_ASYNC16(dst, src) \
    asm volatile("cp.async.cg.shared.global [%0], [%1], 16;" :: "r"(dst), "l"(src) : "memory")
#define CP_COMMIT() asm volatile("cp.async.commit_group;" ::: "memory")
#define CP_WAIT1()  asm volatile("cp.async.wait_group 1;" ::: "memory")
#define CP_WAIT0()  asm volatile("cp.async.wait_group 0;" ::: "memory")

#define MMA_TF32(c, a, b) \
    asm volatile("mma.sync.aligned.m16n8k8.row.col.f32.tf32.tf32.f32 " \
        "{%0,%1,%2,%3}, {%4,%5,%6,%7}, {%8,%9}, {%0,%1,%2,%3};" \
        : "+f"((c)[0]), "+f"((c)[1]), "+f"((c)[2]), "+f"((c)[3]) \
        : "r"((a)[0]), "r"((a)[1]), "r"((a)[2]), "r"((a)[3]), "r"((b)[0]), "r"((b)[1]))

#define BM 128
#define BN 128
#define BK 32
#define STG_FLOATS ((BM + BN) * 32)     // 8192
#define STG_BYTES  (STG_FLOATS * 4)     // 32768
#define GEMM_SMEM  (3 * STG_BYTES)      // 98304

// ---------------------------------------------------------------------------
// fragment loader: one ks step's A (4 mi) + B (4 ni) fragments
// ---------------------------------------------------------------------------
__device__ __forceinline__ void ldfrag(const float* __restrict__ As,
                                       const float* __restrict__ Bs,
                                       int off, uint32_t af[4][4], uint32_t bf[4][2])
{
#pragma unroll
    for (int mi = 0; mi < 4; mi++) {
        float2 lo = *reinterpret_cast<const float2*>(As + mi * 512 + off);
        float2 hi = *reinterpret_cast<const float2*>(As + mi * 512 + 256 + off);
        af[mi][0] = __float_as_uint(lo.x);
        af[mi][1] = __float_as_uint(hi.x);
        af[mi][2] = __float_as_uint(lo.y);
        af[mi][3] = __float_as_uint(hi.y);
    }
#pragma unroll
    for (int ni = 0; ni < 4; ni++) {
        float2 b = *reinterpret_cast<const float2*>(Bs + ni * 256 + off);
        bf[ni][0] = __float_as_uint(b.x);
        bf[ni][1] = __float_as_uint(b.y);
    }
}

// ---------------------------------------------------------------------------
// Shared mainloop: acc += A[m0:m0+128, :K] @ B[n0:n0+128, :K]^T
// (A,B pre-offset to their tile rows; both k-p8-permuted in gmem)
// Fragments double-buffered: ks+1 loads issue before ks MMAs.
// ---------------------------------------------------------------------------
__device__ __forceinline__ void tf32_mainloop(
    const float* __restrict__ A, const float* __restrict__ B,
    int K, float* sm, uint32_t sb, int tid, float acc[4][4][4])
{
    const int wid  = tid >> 5, lane = tid & 31;
    const int g    = lane >> 2, t4 = lane & 3;
    const int wm   = wid & 1,  wn = wid >> 1;

    auto load_stage = [&](int kt, int s) {
        const uint32_t st = sb + s * STG_BYTES;
        const int k0 = kt * BK;
#pragma unroll
        for (int i = 0; i < 4; i++) {          // A: 128 rows x 8 chunks of 16B
            int id = tid + i * 256, r = id >> 3, c = id & 7;
            CP_ASYNC16(st + r * 128 + ((c ^ ((r & 3) << 1)) * 16),
                       A + (size_t)r * K + k0 + c * 4);
        }
#pragma unroll
        for (int i = 0; i < 4; i++) {          // B: 128 rows x 8 chunks
            int id = tid + i * 256, r = id >> 3, c = id & 7;
            CP_ASYNC16(st + BM * 128 + r * 128 + ((c ^ ((r & 3) << 1)) * 16),
                       B + (size_t)r * K + k0 + c * 4);
        }
        CP_COMMIT();
    };

    int off[4];
#pragma unroll
    for (int ks = 0; ks < 4; ks++)
        off[ks] = (((2 * ks + (t4 >> 1)) ^ ((g & 3) << 1)) << 2) | ((t4 & 1) << 1);

    const float* aBase = sm + (wm * 64 + g) * 32;
    const float* bBase = sm + BM * 32 + (wn * 32 + g) * 32;

    const int KT = K / BK;
    load_stage(0, 0);
    load_stage(1, 1);

    for (int kt = 0; kt < KT; kt++) {
        if (kt + 1 < KT) { CP_WAIT1(); } else { CP_WAIT0(); }
        __syncthreads();
        if (kt + 2 < KT) load_stage(kt + 2, (kt + 2) % 3);

        const float* As = aBase + (kt % 3) * STG_FLOATS;
        const float* Bs = bBase + (kt % 3) * STG_FLOATS;

        uint32_t af[2][4][4], bf[2][4][2];
        ldfrag(As, Bs, off[0], af[0], bf[0]);

#pragma unroll
        for (int ks = 0; ks < 4; ks++) {
            const int cur = ks & 1;
            if (ks < 3) ldfrag(As, Bs, off[ks + 1], af[cur ^ 1], bf[cur ^ 1]);
#pragma unroll
            for (int mi = 0; mi < 4; mi++)
#pragma unroll
                for (int ni = 0; ni < 4; ni++)
                    MMA_TF32(acc[mi][ni], af[cur][mi], bf[cur][ni]);
        }
    }
}

// ---- epilogue helpers ------------------------------------------------------
// MODE1: tf32-rounded, columns p8-permuted (output is a k-dim downstream)
__device__ __forceinline__ void epi_mode1(
    float acc[4][4][4], float* __restrict__ C, const float* __restrict__ bias,
    int m0, int n0, int N, float alpha, int tid, bool has_bias)
{
    const int wid = tid >> 5, lane = tid & 31;
    const int g = lane >> 2, t4 = lane & 3;
    const int wm = wid & 1, wn = wid >> 1;
    const int q0 = ((2 * t4 & 3) << 1) | ((2 * t4) >> 2);
    const int q1 = (((2 * t4 + 1) & 3) << 1) | ((2 * t4 + 1) >> 2);
#pragma unroll
    for (int mi = 0; mi < 4; mi++) {
        const int row = m0 + wm * 64 + mi * 16 + g;
#pragma unroll
        for (int ni = 0; ni < 4; ni++) {
            const int colb = n0 + wn * 32 + ni * 8;
            float b0 = has_bias ? __ldg(bias + colb + 2 * t4)     : 0.0f;
            float b1 = has_bias ? __ldg(bias + colb + 2 * t4 + 1) : 0.0f;
            C[(size_t)row * N + colb + q0]       = tf32r(acc[mi][ni][0] * alpha + b0);
            C[(size_t)row * N + colb + q1]       = tf32r(acc[mi][ni][1] * alpha + b1);
            C[(size_t)(row + 8) * N + colb + q0] = tf32r(acc[mi][ni][2] * alpha + b0);
            C[(size_t)(row + 8) * N + colb + q1] = tf32r(acc[mi][ni][3] * alpha + b1);
        }
    }
}

// MODE2: rounded + transposed -> Vt[b][col][p8(tok)]
__device__ __forceinline__ void epi_mode2(
    float acc[4][4][4], float* __restrict__ Cb, const float* __restrict__ bias,
    int m0, int n0, int tid)
{
    const int wid = tid >> 5, lane = tid & 31;
    const int g = lane >> 2, t4 = lane & 3;
    const int wm = wid & 1, wn = wid >> 1;
    const int pg = ((g & 3) << 1) | (g >> 2);
    const int tokbase = (m0 % TSEQ) + wm * 64 + pg;
#pragma unroll
    for (int mi = 0; mi < 4; mi++) {
        const int tok = tokbase + mi * 16;
#pragma unroll
        for (int ni = 0; ni < 4; ni++) {
            const int col = n0 + wn * 32 + ni * 8 + t4 * 2;
            float b0 = __ldg(bias + col);
            float b1 = __ldg(bias + col + 1);
            Cb[(size_t)col * TSEQ + tok]           = tf32r(acc[mi][ni][0] + b0);
            Cb[(size_t)(col + 1) * TSEQ + tok]     = tf32r(acc[mi][ni][1] + b1);
            Cb[(size_t)col * TSEQ + tok + 8]       = tf32r(acc[mi][ni][2] + b0);
            Cb[(size_t)(col + 1) * TSEQ + tok + 8] = tf32r(acc[mi][ni][3] + b1);
        }
    }
}

// ---------------------------------------------------------------------------
// Generic GEMM kernel (MODE 0: plain fp32 out; MODE 1: rounded+permuted out)
// ---------------------------------------------------------------------------
template <int MODE, bool HAS_BIAS>
__global__ __launch_bounds__(256, 2)
void tf32_gemm(const float* __restrict__ A, const float* __restrict__ B,
               const float* __restrict__ bias, float* __restrict__ C,
               int M, int N, int K, float alpha,
               size_t sA, size_t sB, size_t sC)
{
    extern __shared__ float sm[];
    const uint32_t sb = smem_u32(sm);
    const int tid = threadIdx.x;

    const int m0 = blockIdx.y * BM;
    const int n0 = blockIdx.x * BN;
    A += (size_t)blockIdx.z * sA + (size_t)m0 * K;
    B += (size_t)blockIdx.z * sB + (size_t)n0 * K;

    float acc[4][4][4];
#pragma unroll
    for (int mi = 0; mi < 4; mi++)
#pragma unroll
        for (int ni = 0; ni < 4; ni++)
#pragma unroll
            for (int r = 0; r < 4; r++) acc[mi][ni][r] = 0.0f;

    tf32_mainloop(A, B, K, sm, sb, tid, acc);

    C += (size_t)blockIdx.z * sC;
    if (MODE == 1) {
        epi_mode1(acc, C, bias, m0, n0, N, alpha, tid, HAS_BIAS);
    } else {
        const int wid = tid >> 5, lane = tid & 31;
        const int g = lane >> 2, t4 = lane & 3;
        const int wm = wid & 1, wn = wid >> 1;
#pragma unroll
        for (int mi = 0; mi < 4; mi++) {
            const int row = m0 + wm * 64 + mi * 16 + g;
#pragma unroll
            for (int ni = 0; ni < 4; ni++) {
                const int col = n0 + wn * 32 + ni * 8 + t4 * 2;
                float b0 = HAS_BIAS ? __ldg(bias + col)     : 0.0f;
                float b1 = HAS_BIAS ? __ldg(bias + col + 1) : 0.0f;
                float f0 = acc[mi][ni][0] * alpha + b0;
                float f1 = acc[mi][ni][1] * alpha + b1;
                float f2 = acc[mi][ni][2] * alpha + b0;
                float f3 = acc[mi][ni][3] * alpha + b1;
                *reinterpret_cast<float2*>(C + (size_t)row * N + col)       = make_float2(f0, f1);
                *reinterpret_cast<float2*>(C + (size_t)(row + 8) * N + col) = make_float2(f2, f3);
            }
        }
    }
}

// ---------------------------------------------------------------------------
// Fused Q/K/V projection: one launch, 3 segments along grid.x.
// ---------------------------------------------------------------------------
__global__ __launch_bounds__(256, 2)
void proj_fused(const float* __restrict__ T, const float* __restrict__ Src,
                const float* __restrict__ W,
                const float* __restrict__ bq, const float* __restrict__ bk,
                const float* __restrict__ bv,
                float* __restrict__ Q, float* __restrict__ Kb,
                float* __restrict__ Vt)
{
    extern __shared__ float sm[];
    const uint32_t sb = smem_u32(sm);
    const int tid = threadIdx.x;

    const int seg = blockIdx.x >> 3;             // EMB/BN = 8 tiles per segment
    const int n0  = (blockIdx.x & 7) * BN;
    const int m0  = blockIdx.y * BM;

    const float* A = (seg == 0) ? T : Src;
    const float* B = W + (size_t)seg * EMB * EMB;
    A += (size_t)m0 * EMB;
    B += (size_t)n0 * EMB;

    float acc[4][4][4];
#pragma unroll
    for (int mi = 0; mi < 4; mi++)
#pragma unroll
        for (int ni = 0; ni < 4; ni++)
#pragma unroll
            for (int r = 0; r < 4; r++) acc[mi][ni][r] = 0.0f;

    tf32_mainloop(A, B, EMB, sm, sb, tid, acc);

    if (seg == 0) {
        epi_mode1(acc, Q, bq, m0, n0, EMB, 1.0f, tid, true);
    } else if (seg == 1) {
        epi_mode1(acc, Kb, bk, m0, n0, EMB, 1.0f, tid, true);
    } else {
        float* Cb = Vt + (size_t)(m0 / TSEQ) * EMB * TSEQ;
        epi_mode2(acc, Cb, bv, m0, n0, tid);
    }
}

// ---------------------------------------------------------------------------
// rounding passes: tf32-round AND k-permute (8 elements per thread)
// ---------------------------------------------------------------------------
__device__ __forceinline__ void round_perm8(float4 i0, float4 i1,
                                            float4& o0, float4& o1)
{
    o0 = make_float4(tf32r(i0.x), tf32r(i1.x), tf32r(i0.y), tf32r(i1.y));
    o1 = make_float4(tf32r(i0.z), tf32r(i1.z), tf32r(i0.w), tf32r(i1.w));
}

__global__ void round_act_kernel(const float4* __restrict__ a, float4* __restrict__ ya,
                                 const float4* __restrict__ b, float4* __restrict__ yb,
                                 int n8)
{
    int i = blockIdx.x * blockDim.x + threadIdx.x;
    if (i >= n8) return;
    const float4* x = blockIdx.y ? b : a;
    float4*       y = blockIdx.y ? yb : ya;
    float4 o0, o1;
    round_perm8(x[2 * i], x[2 * i + 1], o0, o1);
    y[2 * i] = o0; y[2 * i + 1] = o1;
}

__global__ void round_w_kernel(const float4* __restrict__ w0, const float4* __restrict__ w1,
                               const float4* __restrict__ w2, const float4* __restrict__ w3,
                               float4* __restrict__ y, int n8)
{
    int i = blockIdx.x * blockDim.x + threadIdx.x;
    if (i >= n8) return;
    const float4* src = (blockIdx.y == 0) ? w0 : (blockIdx.y == 1) ? w1
                      : (blockIdx.y == 2) ? w2 : w3;
    float4 o0, o1;
    round_perm8(src[2 * i], src[2 * i + 1], o0, o1);
    y[(size_t)blockIdx.y * 2 * n8 + 2 * i]     = o0;
    y[(size_t)blockIdx.y * 2 * n8 + 2 * i + 1] = o1;
}

// ---------------------------------------------------------------------------
// softmax over 2048-length rows (in place): reads true-order S, writes
// tf32-rounded P with k-permuted columns. 8 elements per thread.
// ---------------------------------------------------------------------------
__device__ __forceinline__ float blk_red_max(float v) {
    __shared__ float sh[8]; __shared__ float res;
    const int lane = threadIdx.x & 31, warp = threadIdx.x >> 5;
#pragma unroll
    for (int o = 16; o > 0; o >>= 1) v = fmaxf(v, __shfl_xor_sync(0xffffffffu, v, o));
    if (lane == 0) sh[warp] = v;
    __syncthreads();
    if (warp == 0) {
        float w = (lane < 8) ? sh[lane] : -3.0e38f;
#pragma unroll
        for (int o = 4; o > 0; o >>= 1) w = fmaxf(w, __shfl_xor_sync(0xffffffffu, w, o));
        if (lane == 0) res = w;
    }
    __syncthreads();
    return res;
}
__device__ __forceinline__ float blk_red_sum(float v) {
    __shared__ float sh[8]; __shared__ float res;
    const int lane = threadIdx.x & 31, warp = threadIdx.x >> 5;
#pragma unroll
    for (int o = 16; o > 0; o >>= 1) v += __shfl_xor_sync(0xffffffffu, v, o);
    if (lane == 0) sh[warp] = v;
    __syncthreads();
    if (warp == 0) {
        float w = (lane < 8) ? sh[lane] : 0.0f;
#pragma unroll
        for (int o = 4; o > 0; o >>= 1) w += __shfl_xor_sync(0xffffffffu, w, o);
        if (lane == 0) res = w;
    }
    __syncthreads();
    return res;
}

__global__ __launch_bounds__(256)
void softmax_kernel(float* __restrict__ S)
{
    float4* row = reinterpret_cast<float4*>(S + (size_t)blockIdx.x * TSEQ);
    const int t = threadIdx.x;

    float4 v0 = row[2 * t];
    float4 v1 = row[2 * t + 1];

    float mx = fmaxf(fmaxf(fmaxf(v0.x, v0.y), fmaxf(v0.z, v0.w)),
                     fmaxf(fmaxf(v1.x, v1.y), fmaxf(v1.z, v1.w)));
    mx = blk_red_max(mx);

    v0.x = __expf(v0.x - mx); v0.y = __expf(v0.y - mx);
    v0.z = __expf(v0.z - mx); v0.w = __expf(v0.w - mx);
    v1.x = __expf(v1.x - mx); v1.y = __expf(v1.y - mx);
    v1.z = __expf(v1.z - mx); v1.w = __expf(v1.w - mx);

    float s = (v0.x + v0.y + v0.z + v0.w) + (v1.x + v1.y + v1.z + v1.w);
    s = blk_red_sum(s);
    const float inv = 1.0f / s;

    v0.x *= inv; v0.y *= inv; v0.z *= inv; v0.w *= inv;
    v1.x *= inv; v1.y *= inv; v1.z *= inv; v1.w *= inv;

    float4 o0, o1;
    round_perm8(v0, v1, o0, o1);
    row[2 * t]     = o0;
    row[2 * t + 1] = o1;
}

// ---------------------------------------------------------------------------
extern "C" void kernel_launch(void* const* d_in, const int* in_sizes, int n_in,
                              void* d_out, int out_size)
{
    const float* target = (const float*)d_in[0];
    const float* source = (const float*)d_in[1];
    const float* Wq = (const float*)d_in[2];
    const float* bq = (const float*)d_in[3];
    const float* Wk = (const float*)d_in[4];
    const float* bk = (const float*)d_in[5];
    const float* Wv = (const float*)d_in[6];
    const float* bv = (const float*)d_in[7];
    const float* Wo = (const float*)d_in[8];
    const float* bo = (const float*)d_in[9];
    float* out = (float*)d_out;

    float *T, *Src, *W, *Q, *Kb, *Vt, *S, *O;
    cudaGetSymbolAddress((void**)&T,   g_T);
    cudaGetSymbolAddress((void**)&Src, g_Src);
    cudaGetSymbolAddress((void**)&W,   g_W);
    cudaGetSymbolAddress((void**)&Q,   g_Q);
    cudaGetSymbolAddress((void**)&Kb,  g_K);
    cudaGetSymbolAddress((void**)&Vt,  g_Vt);
    cudaGetSymbolAddress((void**)&S,   g_S);
    cudaGetSymbolAddress((void**)&O,   g_O);

    cudaFuncSetAttribute(tf32_gemm<0, false>, cudaFuncAttributeMaxDynamicSharedMemorySize, GEMM_SMEM);
    cudaFuncSetAttribute(tf32_gemm<0, true>,  cudaFuncAttributeMaxDynamicSharedMemorySize, GEMM_SMEM);
    cudaFuncSetAttribute(tf32_gemm<1, false>, cudaFuncAttributeMaxDynamicSharedMemorySize, GEMM_SMEM);
    cudaFuncSetAttribute(proj_fused,          cudaFuncAttributeMaxDynamicSharedMemorySize, GEMM_SMEM);

    // launch 0-1: tf32-round + p8-permute inputs and weights
    {
        dim3 ga((unsigned)(NELEM / 8 / 256), 2, 1);
        round_act_kernel<<<ga, 256>>>((const float4*)target, (float4*)T,
                                      (const float4*)source, (float4*)Src,
                                      (int)(NELEM / 8));
        dim3 gw((unsigned)(EMB * EMB / 8 / 256), 4, 1);
        round_w_kernel<<<gw, 256>>>((const float4*)Wq, (const float4*)Wk,
                                    (const float4*)Wv, (const float4*)Wo,
                                    (float4*)W, EMB * EMB / 8);
    }

    const float scale = 1.0f / 32.0f;  // 1/sqrt(1024)

    // launch 2: fused Q/K/V projections
    {
        dim3 grd(24, MTOT / BM, 1);
        proj_fused<<<grd, 256, GEMM_SMEM>>>(T, Src, W, bq, bk, bv, Q, Kb, Vt);
    }

    // launch 3: S = Q @ K^T / 32 (batched)
    {
        dim3 grd(TSEQ / BN, TSEQ / BM, BATCH);
        tf32_gemm<0, false><<<grd, 256, GEMM_SMEM>>>(Q, Kb, nullptr, S,
            TSEQ, TSEQ, EMB, scale,
            (size_t)TSEQ * EMB, (size_t)TSEQ * EMB, (size_t)TSEQ * TSEQ);
    }

    // launch 4: P = softmax(S) in place (rounded + k-permuted)
    softmax_kernel<<<BATCH * TSEQ, 256>>>(S);

    // launch 5 (ncu -s 5 -c 1 captures this): O = P @ Vt^T (batched, K=2048)
    {
        dim3 grd(EMB / BN, TSEQ / BM, BATCH);
        tf32_gemm<1, false><<<grd, 256, GEMM_SMEM>>>(S, Vt, nullptr, O,
            TSEQ, EMB, TSEQ, 1.0f,
            (size_t)TSEQ * TSEQ, (size_t)EMB * TSEQ, (size_t)TSEQ * EMB);
    }

    // launch 6: out = O @ Wo^T + bo (fp32, true order)
    {
        dim3 grd(EMB / BN, MTOT / BM, 1);
        tf32_gemm<0, true><<<grd, 256, GEMM_SMEM>>>(O, W + 3u * EMB * EMB, bo, out,
                                                    MTOT, EMB, EMB, 1.0f, 0, 0, 0);
    }
}